// round 1
// baseline (speedup 1.0000x reference)
#include <cuda_runtime.h>
#include <math.h>

#define Bn 16
#define Cn 3
#define Hn 512
#define Wn 512
#define HW (Hn * Wn)           // 262144
#define CHW (Cn * HW)          // 786432
#define NTOT (Bn * Cn * HW)    // 12582912

// Scratch (no allocations allowed in kernel_launch)
__device__ float  g_rdet[Bn * HW];   // signed residual_sr: sign bit = mask (residual_sr < residual_ema)
__device__ double g_sum[Bn];
__device__ double g_sumsq[Bn];
__device__ float  g_patchw[Bn];

// ---------------------------------------------------------------------------
__global__ void zero_kernel(float* out) {
    int i = threadIdx.x;
    if (i < Bn) { g_sum[i] = 0.0; g_sumsq[i] = 0.0; }
    if (i == 0) out[0] = 0.0f;
}

// ---------------------------------------------------------------------------
// One block handles a 1024-pixel chunk of one batch image (4 px/thread, 256 thr).
// Grid: Bn * (HW/1024) = 16 * 256 = 4096 blocks.
__global__ __launch_bounds__(256) void residual_kernel(
    const float* __restrict__ sr,
    const float* __restrict__ srema,
    const float* __restrict__ hr)
{
    const int BLOCKS_PER_B = HW / 1024;            // 256
    const int b     = blockIdx.x / BLOCKS_PER_B;
    const int chunk = blockIdx.x % BLOCKS_PER_B;
    const int tid   = threadIdx.x;

    const long base = (long)b * CHW;
    float lsum = 0.f, lsq = 0.f;

#pragma unroll
    for (int k = 0; k < 4; ++k) {
        int p   = chunk * 1024 + k * 256 + tid;    // pixel index in [0, HW)
        long ix = base + p;
        float rs = 0.f, re = 0.f;
#pragma unroll
        for (int c = 0; c < Cn; ++c) {
            float h  = __ldg(hr    + ix + (long)c * HW);
            float s  = __ldg(sr    + ix + (long)c * HW);
            float se = __ldg(srema + ix + (long)c * HW);
            rs += fabsf(h - s);
            re += fabsf(h - se);
        }
        rs *= (1.0f / 255.0f);
        re *= (1.0f / 255.0f);
        // Fold mask into sign bit. rs >= 0, so -0.0f encodes "masked, value 0".
        float stored = (rs < re) ? __int_as_float(__float_as_int(rs) | 0x80000000u) : rs;
        g_rdet[b * HW + p] = stored;
        lsum += rs;
        lsq  += rs * rs;
    }

    // Block reduction (fp32), then double atomics per batch.
    __shared__ float ssum[256], ssq[256];
    ssum[tid] = lsum; ssq[tid] = lsq;
    __syncthreads();
    for (int s = 128; s > 0; s >>= 1) {
        if (tid < s) { ssum[tid] += ssum[tid + s]; ssq[tid] += ssq[tid + s]; }
        __syncthreads();
    }
    if (tid == 0) {
        atomicAdd(&g_sum[b],   (double)ssum[0]);
        atomicAdd(&g_sumsq[b], (double)ssq[0]);
    }
}

// ---------------------------------------------------------------------------
__global__ void patchw_kernel() {
    int b = threadIdx.x;
    if (b < Bn) {
        const double n = (double)HW;
        double var = (g_sumsq[b] - g_sum[b] * g_sum[b] / n) / (n - 1.0);
        if (var < 0.0) var = 0.0;
        g_patchw[b] = (float)pow(var, 0.2);
    }
}

// ---------------------------------------------------------------------------
// Per pixel: 3x3 reflect-padded unbiased local variance over |r_det|,
// weight = patch_w * local_var, zeroed by sign-bit mask,
// loss contribution = |weight| * 255 * |r_det_center|.
// Block 32x8, grid (16, 64, 16).
__global__ __launch_bounds__(256) void loss_kernel(float* __restrict__ out) {
    const int w = blockIdx.x * 32 + threadIdx.x;
    const int h = blockIdx.y * 8  + threadIdx.y;
    const int b = blockIdx.z;

    const float* __restrict__ r = g_rdet + b * HW;

    // reflect padding indices (pad = 1, mode "reflect": -1 -> 1, H -> H-2)
    const int hm = (h == 0)      ? 1      : h - 1;
    const int hp = (h == Hn - 1) ? Hn - 2 : h + 1;
    const int wm = (w == 0)      ? 1      : w - 1;
    const int wp = (w == Wn - 1) ? Wn - 2 : w + 1;

    float center_s = r[h * Wn + w];

    float v0 = fabsf(r[hm * Wn + wm]);
    float v1 = fabsf(r[hm * Wn + w ]);
    float v2 = fabsf(r[hm * Wn + wp]);
    float v3 = fabsf(r[h  * Wn + wm]);
    float v4 = fabsf(center_s);
    float v5 = fabsf(r[h  * Wn + wp]);
    float v6 = fabsf(r[hp * Wn + wm]);
    float v7 = fabsf(r[hp * Wn + w ]);
    float v8 = fabsf(r[hp * Wn + wp]);

    float s  = v0 + v1 + v2 + v3 + v4 + v5 + v6 + v7 + v8;
    float sq = v0*v0 + v1*v1 + v2*v2 + v3*v3 + v4*v4
             + v5*v5 + v6*v6 + v7*v7 + v8*v8;

    float lv  = (sq - s * s * (1.0f / 9.0f)) * (1.0f / 8.0f);  // unbiased, n=9
    float wgt = g_patchw[b] * lv;
    if (signbit(center_s)) wgt = 0.0f;

    // sum_c |w*sr - w*hr| = |w| * 255 * r_det
    float contrib = fabsf(wgt) * 255.0f * v4;

    // Reduce within block
    __shared__ float sh[256];
    int tid = threadIdx.y * 32 + threadIdx.x;
    sh[tid] = contrib;
    __syncthreads();
    for (int st = 128; st > 0; st >>= 1) {
        if (tid < st) sh[tid] += sh[tid + st];
        __syncthreads();
    }
    if (tid == 0) atomicAdd(out, sh[0] * (1.0f / (float)NTOT));
}

// ---------------------------------------------------------------------------
extern "C" void kernel_launch(void* const* d_in, const int* in_sizes, int n_in,
                              void* d_out, int out_size) {
    const float* sr    = (const float*)d_in[0];
    const float* srema = (const float*)d_in[1];
    const float* hr    = (const float*)d_in[2];
    float* out = (float*)d_out;

    zero_kernel<<<1, 32>>>(out);
    residual_kernel<<<Bn * (HW / 1024), 256>>>(sr, srema, hr);
    patchw_kernel<<<1, 32>>>();
    dim3 blk(32, 8, 1);
    dim3 grd(Wn / 32, Hn / 8, Bn);
    loss_kernel<<<grd, blk>>>(out);
}

// round 2
// speedup vs baseline: 1.5424x; 1.5424x over previous
#include <cuda_runtime.h>
#include <math.h>

#define Bn 16
#define Cn 3
#define Hn 512
#define Wn 512
#define HW (Hn * Wn)           // 262144
#define CHW (Cn * HW)          // 786432
#define NTOT (Bn * Cn * HW)    // 12582912

#define TW 64                  // owned tile width
#define TH 32                  // owned tile height
#define HTW (TW + 2)           // 66 (halo)
#define HTH (TH + 2)           // 34 (halo)
#define NTHREADS 256
#define PIX_PER_THREAD ((TW * TH) / NTHREADS)   // 8

// Per-batch accumulators (no allocations allowed)
__device__ double g_sum[Bn];    // sum of r_det (owned pixels, exactly once)
__device__ double g_sumsq[Bn];  // sum of r_det^2
__device__ double g_S[Bn];      // sum of |local_var| * r * mask  (patch_w deferred)

// ---------------------------------------------------------------------------
__global__ void zero_kernel() {
    int i = threadIdx.x;
    if (i < Bn) { g_sum[i] = 0.0; g_sumsq[i] = 0.0; g_S[i] = 0.0; }
}

// ---------------------------------------------------------------------------
// One block: compute signed residual for a (TH+2)x(TW+2) halo tile from
// sr/sr_ema/hr (reflect padding at image borders), then local 3x3 unbiased
// variance + loss contribution for the owned TWxTH interior.
// Grid: (Wn/TW, Hn/TH, Bn) = (8, 16, 16) = 2048 blocks.
__global__ __launch_bounds__(NTHREADS) void fused_kernel(
    const float* __restrict__ sr,
    const float* __restrict__ srema,
    const float* __restrict__ hr)
{
    __shared__ float rt[HTH * HTW];        // signed r_det tile (sign bit = mask)
    __shared__ float red[3 * NTHREADS];    // block reduction scratch

    const int tid = threadIdx.x;
    const int w0  = blockIdx.x * TW;
    const int h0  = blockIdx.y * TH;
    const int b   = blockIdx.z;
    const long base = (long)b * CHW;

    // --- Phase 1: build halo tile of signed residuals -----------------------
    for (int t = tid; t < HTH * HTW; t += NTHREADS) {
        int ty = t / HTW;
        int tx = t - ty * HTW;
        int gh = h0 - 1 + ty;
        int gw = w0 - 1 + tx;
        // reflect padding (pad=1): -1 -> 1, N -> N-2
        gh = (gh < 0) ? -gh : ((gh >= Hn) ? 2 * Hn - 2 - gh : gh);
        gw = (gw < 0) ? -gw : ((gw >= Wn) ? 2 * Wn - 2 - gw : gw);
        long ix = base + (long)gh * Wn + gw;
        float rs = 0.f, re = 0.f;
#pragma unroll
        for (int c = 0; c < Cn; ++c) {
            float h  = __ldg(hr    + ix + (long)c * HW);
            float s  = __ldg(sr    + ix + (long)c * HW);
            float se = __ldg(srema + ix + (long)c * HW);
            rs += fabsf(h - s);
            re += fabsf(h - se);
        }
        rs *= (1.0f / 255.0f);
        re *= (1.0f / 255.0f);
        // mask folded into sign bit (rs >= 0 always)
        rt[t] = (rs < re) ? __int_as_float(__float_as_int(rs) | 0x80000000u) : rs;
    }
    __syncthreads();

    // --- Phase 2: local variance + contribution over owned pixels -----------
    float lsum = 0.f, lsq = 0.f, lS = 0.f;
#pragma unroll
    for (int k = 0; k < PIX_PER_THREAD; ++k) {
        int p   = tid + k * NTHREADS;
        int row = p / TW;              // 0..TH-1
        int col = p - row * TW;        // 0..TW-1
        const float* r0 = rt + row * HTW + col;   // window top-left in halo coords
        const float* r1 = r0 + HTW;
        const float* r2 = r1 + HTW;

        float c_s = r1[1];             // signed center
        float v0 = fabsf(r0[0]), v1 = fabsf(r0[1]), v2 = fabsf(r0[2]);
        float v3 = fabsf(r1[0]), v4 = fabsf(c_s),   v5 = fabsf(r1[2]);
        float v6 = fabsf(r2[0]), v7 = fabsf(r2[1]), v8 = fabsf(r2[2]);

        float s  = v0 + v1 + v2 + v3 + v4 + v5 + v6 + v7 + v8;
        float sq = v0*v0 + v1*v1 + v2*v2 + v3*v3 + v4*v4
                 + v5*v5 + v6*v6 + v7*v7 + v8*v8;
        float lv = (sq - s * s * (1.0f / 9.0f)) * (1.0f / 8.0f);

        // contribution (patch_w and 255/NTOT deferred): |lv| * r * mask
        float contrib = signbit(c_s) ? 0.0f : fabsf(lv) * v4;

        lsum += v4;
        lsq  += v4 * v4;
        lS   += contrib;
    }

    // --- Block reduction + per-batch double atomics --------------------------
    red[tid]               = lsum;
    red[tid + NTHREADS]    = lsq;
    red[tid + 2*NTHREADS]  = lS;
    __syncthreads();
    for (int st = NTHREADS / 2; st > 0; st >>= 1) {
        if (tid < st) {
            red[tid]              += red[tid + st];
            red[tid + NTHREADS]   += red[tid + NTHREADS + st];
            red[tid + 2*NTHREADS] += red[tid + 2*NTHREADS + st];
        }
        __syncthreads();
    }
    if (tid == 0) {
        atomicAdd(&g_sum[b],   (double)red[0]);
        atomicAdd(&g_sumsq[b], (double)red[NTHREADS]);
        atomicAdd(&g_S[b],     (double)red[2*NTHREADS]);
    }
}

// ---------------------------------------------------------------------------
// loss = (255 / NTOT) * sum_b  patch_var_b^0.2 * S_b
__global__ void final_kernel(float* __restrict__ out) {
    int b = threadIdx.x;
    double acc = 0.0;
    if (b < Bn) {
        const double n = (double)HW;
        double var = (g_sumsq[b] - g_sum[b] * g_sum[b] / n) / (n - 1.0);
        if (var < 0.0) var = 0.0;
        acc = pow(var, 0.2) * g_S[b];
    }
#pragma unroll
    for (int o = 16; o > 0; o >>= 1)
        acc += __shfl_down_sync(0xffffffff, acc, o);
    if (b == 0) out[0] = (float)(acc * 255.0 / (double)NTOT);
}

// ---------------------------------------------------------------------------
extern "C" void kernel_launch(void* const* d_in, const int* in_sizes, int n_in,
                              void* d_out, int out_size) {
    const float* sr    = (const float*)d_in[0];
    const float* srema = (const float*)d_in[1];
    const float* hr    = (const float*)d_in[2];
    float* out = (float*)d_out;

    zero_kernel<<<1, 32>>>();
    dim3 blk(NTHREADS, 1, 1);
    dim3 grd(Wn / TW, Hn / TH, Bn);
    fused_kernel<<<grd, blk>>>(sr, srema, hr);
    final_kernel<<<1, 32>>>(out);
}